// round 1
// baseline (speedup 1.0000x reference)
#include <cuda_runtime.h>

// Problem constants: pred [1,81,3,480,832] f32, mask [1,81,480,832] f32, scalar f32 out.
#define T_FRAMES 81
#define CCH 3
#define HDIM 480
#define WDIM 832
#define HW (HDIM * WDIM)          // 399360
#define CHW (CCH * HW)            // 1198080

#define N1 80
#define N4 77
#define N8 73
#define N16 65
#define BASE1 0
#define BASE4 (N1)                 // 80
#define BASE8 (N1 + N4)            // 157
#define BASE16 (N1 + N4 + N8)      // 230
#define NSLOTS (N1 + N4 + N8 + N16) // 295

// Global accumulators: num[slot], den[slot] (den = sum of per-pixel weight; x3 + 1e-6 later)
__device__ float g_num[NSLOTS];
__device__ float g_den[NSLOTS];

__device__ __forceinline__ float fsqrta(float x) {
    float y;
    asm("sqrt.approx.f32 %0, %1;" : "=f"(y) : "f"(x));
    return y;
}

// One (t, scale) pair contribution for this thread's 2 pixels, warp-reduced, RED to global.
// J = static circular-window index of the lagged frame; t_ / SVAL are runtime/const.
#define PAIR(J, SBASE, SVAL) do {                                              \
    float dx_, dy_, fdx_, fdy_;                                                \
    dx_ = c0.x - wp0[(J)].x; fdx_  = fsqrta(__fmaf_rn(dx_, dx_, 1e-6f));       \
    dy_ = c0.y - wp0[(J)].y; fdy_  = fsqrta(__fmaf_rn(dy_, dy_, 1e-6f));       \
    dx_ = c1.x - wp1[(J)].x; fdx_ += fsqrta(__fmaf_rn(dx_, dx_, 1e-6f));       \
    dy_ = c1.y - wp1[(J)].y; fdy_ += fsqrta(__fmaf_rn(dy_, dy_, 1e-6f));       \
    dx_ = c2.x - wp2[(J)].x; fdx_ += fsqrta(__fmaf_rn(dx_, dx_, 1e-6f));       \
    dy_ = c2.y - wp2[(J)].y; fdy_ += fsqrta(__fmaf_rn(dy_, dy_, 1e-6f));       \
    float ux_ = fminf(cm.x + wm[(J)].x, 1.0f);                                 \
    float uy_ = fminf(cm.y + wm[(J)].y, 1.0f);                                 \
    float wx_ = __fmaf_rn(ux_, -0.85f, 1.0f);                                  \
    float wy_ = __fmaf_rn(uy_, -0.85f, 1.0f);                                  \
    float nm_ = __fmaf_rn(fdy_, wy_, fdx_ * wx_);                              \
    float dn_ = wx_ + wy_;                                                     \
    nm_ += __shfl_xor_sync(0xffffffffu, nm_, 16);                              \
    dn_ += __shfl_xor_sync(0xffffffffu, dn_, 16);                              \
    nm_ += __shfl_xor_sync(0xffffffffu, nm_, 8);                               \
    dn_ += __shfl_xor_sync(0xffffffffu, dn_, 8);                               \
    nm_ += __shfl_xor_sync(0xffffffffu, nm_, 4);                               \
    dn_ += __shfl_xor_sync(0xffffffffu, dn_, 4);                               \
    nm_ += __shfl_xor_sync(0xffffffffu, nm_, 2);                               \
    dn_ += __shfl_xor_sync(0xffffffffu, dn_, 2);                               \
    nm_ += __shfl_xor_sync(0xffffffffu, nm_, 1);                               \
    dn_ += __shfl_xor_sync(0xffffffffu, dn_, 1);                               \
    if (lane == 0) {                                                           \
        const int slot_ = (SBASE) + t_ - (SVAL);                               \
        atomicAdd(&g_num[slot_], nm_);                                         \
        atomicAdd(&g_den[slot_], dn_);                                         \
    }                                                                          \
} while (0)

// One time step: load current frame's 3 channels + mask (float2 = 2 pixels),
// emit pairs for each enabled scale (lag-16 read FIRST, its slot is overwritten below),
// then push current values into the static circular window.
#define STEP(TT, U, D1, D4, D8, D16) do {                                      \
    const int t_ = (TT);                                                       \
    const float2 c0 = *(const float2*)(pred + t_ * CHW + px);                  \
    const float2 c1 = *(const float2*)(pred + t_ * CHW + HW + px);             \
    const float2 c2 = *(const float2*)(pred + t_ * CHW + 2 * HW + px);         \
    const float2 cm = *(const float2*)(mask + t_ * HW + px);                   \
    if (D16) PAIR(((U) + 16 - 16) & 15, BASE16, 16);                           \
    if (D8)  PAIR(((U) + 16 - 8) & 15,  BASE8,  8);                           \
    if (D4)  PAIR(((U) + 16 - 4) & 15,  BASE4,  4);                           \
    if (D1)  PAIR(((U) + 16 - 1) & 15,  BASE1,  1);                           \
    wp0[(U)] = c0; wp1[(U)] = c1; wp2[(U)] = c2; wm[(U)] = cm;                 \
} while (0)

__global__ void __launch_bounds__(128, 2)
temporal_kernel(const float* __restrict__ pred, const float* __restrict__ mask) {
    const int tid = blockIdx.x * 128 + threadIdx.x;   // 0 .. HW/2-1
    const int px  = tid * 2;                          // even pixel index -> float2 aligned
    const int lane = threadIdx.x & 31;

    // 16-deep circular windows (statically indexed after unrolling) -> registers
    float2 wp0[16], wp1[16], wp2[16], wm[16];

    // Prologue: t = 0..15, scales activate as t >= s
    STEP(0,  0,  0, 0, 0, 0);
    STEP(1,  1,  1, 0, 0, 0);
    STEP(2,  2,  1, 0, 0, 0);
    STEP(3,  3,  1, 0, 0, 0);
    STEP(4,  4,  1, 1, 0, 0);
    STEP(5,  5,  1, 1, 0, 0);
    STEP(6,  6,  1, 1, 0, 0);
    STEP(7,  7,  1, 1, 0, 0);
    STEP(8,  8,  1, 1, 1, 0);
    STEP(9,  9,  1, 1, 1, 0);
    STEP(10, 10, 1, 1, 1, 0);
    STEP(11, 11, 1, 1, 1, 0);
    STEP(12, 12, 1, 1, 1, 0);
    STEP(13, 13, 1, 1, 1, 0);
    STEP(14, 14, 1, 1, 1, 0);
    STEP(15, 15, 1, 1, 1, 0);

    // Main: t = 16..79 in 4 chunks of 16 (tb = 16,32,48,64)
    #pragma unroll 1
    for (int tb = 16; tb <= 64; tb += 16) {
        STEP(tb + 0,  0,  1, 1, 1, 1);
        STEP(tb + 1,  1,  1, 1, 1, 1);
        STEP(tb + 2,  2,  1, 1, 1, 1);
        STEP(tb + 3,  3,  1, 1, 1, 1);
        STEP(tb + 4,  4,  1, 1, 1, 1);
        STEP(tb + 5,  5,  1, 1, 1, 1);
        STEP(tb + 6,  6,  1, 1, 1, 1);
        STEP(tb + 7,  7,  1, 1, 1, 1);
        STEP(tb + 8,  8,  1, 1, 1, 1);
        STEP(tb + 9,  9,  1, 1, 1, 1);
        STEP(tb + 10, 10, 1, 1, 1, 1);
        STEP(tb + 11, 11, 1, 1, 1, 1);
        STEP(tb + 12, 12, 1, 1, 1, 1);
        STEP(tb + 13, 13, 1, 1, 1, 1);
        STEP(tb + 14, 14, 1, 1, 1, 1);
        STEP(tb + 15, 15, 1, 1, 1, 1);
    }

    // Epilogue: t = 80 (80 & 15 == 0)
    STEP(80, 0, 1, 1, 1, 1);
}

__global__ void zero_kernel() {
    const int i = threadIdx.x;
    if (i < NSLOTS) {
        g_num[i] = 0.0f;
        g_den[i] = 0.0f;
    }
}

__global__ void finalize_kernel(float* __restrict__ out) {
    __shared__ float sh[512];
    const int i = threadIdx.x;
    float v = 0.0f;
    if (i < NSLOTS) {
        float scale, npair;
        if (i < BASE4)       { scale = 1.0f;  npair = (float)N1; }
        else if (i < BASE8)  { scale = 4.0f;  npair = (float)N4; }
        else if (i < BASE16) { scale = 8.0f;  npair = (float)N8; }
        else                 { scale = 16.0f; npair = (float)N16; }
        const float den = g_den[i] * 3.0f + 1e-6f;  // weight broadcast over C=3 channels
        // total = 0.1 * (1/4) * sum_s [ (1/s) * (1/(T-s)) * sum_t num_t/den_t ]
        v = (g_num[i] / den) * (0.1f / (4.0f * scale * npair));
    }
    sh[i] = v;
    __syncthreads();
    #pragma unroll
    for (int off = 256; off > 0; off >>= 1) {
        if (i < off) sh[i] += sh[i + off];
        __syncthreads();
    }
    if (i == 0) out[0] = sh[0];
}

extern "C" void kernel_launch(void* const* d_in, const int* in_sizes, int n_in,
                              void* d_out, int out_size) {
    const float* pred = (const float*)d_in[0];  // [1,81,3,480,832] f32
    const float* mask = (const float*)d_in[1];  // [1,81,480,832]   f32
    (void)in_sizes; (void)n_in; (void)out_size;

    zero_kernel<<<1, 512>>>();
    temporal_kernel<<<(HW / 2) / 128, 128>>>(pred, mask);  // 1560 blocks x 128 threads
    finalize_kernel<<<1, 512>>>((float*)d_out);
}